// round 12
// baseline (speedup 1.0000x reference)
#include <cuda_runtime.h>
#include <cstdint>

// QConv2d binarized conv via mma.sync IMMA (s8, m16n8k32).
// x(32,64,128,128) f32, w(64,64,3,3) OIHW, stride=2, pad=1 -> out(32,64,64,64) f32.
// R12 (= R11 resubmit; broker failure): conv warp widened to 32 ow
// (2 m16 tiles sharing B frags); pack_x loads staged 8-deep for higher MLP.

#define NB 32
#define CIN 64
#define H 128
#define W 128
#define OC 64
#define OH 64
#define OW 64

__device__ unsigned int g_xlo[NB * H * W];   // 2 MB: channels 0-31 sign bits
__device__ unsigned int g_xhi[NB * H * W];   // 2 MB: channels 32-63 sign bits
// B fragments: [(tap*8 + j)*32 + lane] -> uint4 (b0_k0, b1_k0, b0_k1, b1_k1)
__device__ uint4 g_wfrag[9 * 8 * 32];

// ---------------------------------------------------------------------------
// nibble (4 sign bits) -> 4 packed s8: bit=1 -> +1 (0x01), bit=0 -> -1 (0xFF)
// ---------------------------------------------------------------------------
__device__ __forceinline__ unsigned int expand4(unsigned int nib) {
    unsigned int s = (nib | (nib << 7) | (nib << 14) | (nib << 21)) & 0x01010101u;
    return (s * 0xFEu) ^ 0xFFFFFFFFu;
}

__device__ __forceinline__ void mma_s8(int* c,
    unsigned int a0, unsigned int a1, unsigned int a2, unsigned int a3,
    unsigned int b0, unsigned int b1) {
    asm volatile(
        "mma.sync.aligned.m16n8k32.row.col.s32.s8.s8.s32 "
        "{%0,%1,%2,%3}, {%4,%5,%6,%7}, {%8,%9}, {%0,%1,%2,%3};"
        : "+r"(c[0]), "+r"(c[1]), "+r"(c[2]), "+r"(c[3])
        : "r"(a0), "r"(a1), "r"(a2), "r"(a3), "r"(b0), "r"(b1));
}

// ---------------------------------------------------------------------------
// Pack x v2: staged loads (8 float4 in flight per batch) for MLP ~8-16.
// ---------------------------------------------------------------------------
__global__ void __launch_bounds__(256) pack_x_kernel(const float* __restrict__ x) {
    int g = blockIdx.x * blockDim.x + threadIdx.x;
    int half = g & 1;
    int w4   = ((g >> 1) & 31) * 4;
    int h    = (g >> 6) & 127;
    int n    = g >> 13;

    const float* base = x + ((long)(n * CIN + half * 32) * H + h) * W + w4;

    unsigned int b0 = 0, b1 = 0, b2 = 0, b3 = 0;
#pragma unroll
    for (int c0 = 0; c0 < 32; c0 += 8) {
        float4 v[8];
#pragma unroll
        for (int j = 0; j < 8; j++)
            v[j] = *reinterpret_cast<const float4*>(base + (long)(c0 + j) * (H * W));
#pragma unroll
        for (int j = 0; j < 8; j++) {
            int c = c0 + j;
            b0 |= (unsigned int)(v[j].x >= 0.0f) << c;
            b1 |= (unsigned int)(v[j].y >= 0.0f) << c;
            b2 |= (unsigned int)(v[j].z >= 0.0f) << c;
            b3 |= (unsigned int)(v[j].w >= 0.0f) << c;
        }
    }
    unsigned int* plane = half ? g_xhi : g_xlo;
    uint4 val; val.x = b0; val.y = b1; val.z = b2; val.w = b3;
    *reinterpret_cast<uint4*>(plane + ((long)(n * H + h) * W + w4)) = val;
}

// ---------------------------------------------------------------------------
// Pack w (unchanged from R10, verified ~1.5us)
// ---------------------------------------------------------------------------
__global__ void __launch_bounds__(64) pack_w_kernel(const float* __restrict__ w) {
    __shared__ unsigned int s_lo[9], s_hi[9];
    int o    = blockIdx.x;
    int i    = threadIdx.x;
    int warp = i >> 5;
    int lane = i & 31;

    const float* wr = w + (o * CIN + i) * 9;
    float v[9];
#pragma unroll
    for (int t = 0; t < 9; t++) v[t] = wr[t];

#pragma unroll
    for (int t = 0; t < 9; t++) {
        unsigned int m = __ballot_sync(0xFFFFFFFFu, v[t] >= 0.0f);
        if (lane == 0) { if (warp == 0) s_lo[t] = m; else s_hi[t] = m; }
    }
    __syncthreads();

    if (i < 36) {
        int tap = i >> 2;
        int qc  = i & 3;
        unsigned long long wb =
            (unsigned long long)s_lo[tap] | ((unsigned long long)s_hi[tap] << 32);
        uint4 f;
        f.x = expand4((unsigned int)(wb >> (4 * qc))      & 0xFu);
        f.y = expand4((unsigned int)(wb >> (16 + 4 * qc)) & 0xFu);
        f.z = expand4((unsigned int)(wb >> (32 + 4 * qc)) & 0xFu);
        f.w = expand4((unsigned int)(wb >> (48 + 4 * qc)) & 0xFu);
        g_wfrag[(tap * 8 + (o >> 3)) * 32 + (o & 7) * 4 + qc] = f;
    }
}

// ---------------------------------------------------------------------------
// Conv v2: warp = 32 ow (two m16 tiles) x N=64, K=576. B fragments loaded
// once per (tap, j) and used by both tiles (288 IMMA per 72 B-LDG).
// 4096 warps = 512 CTAs x 256 thr. Pad rows -> s8 zeros.
// ---------------------------------------------------------------------------
__global__ void __launch_bounds__(256) conv_mma_kernel(float* __restrict__ out) {
    int gw   = (blockIdx.x * 256 + threadIdx.x) >> 5;   // 0..4095
    int lane = threadIdx.x & 31;
    int owh  = (gw & 1) * 32;       // ow half: tile0 = owh..+15, tile1 = +16..+31
    int oh   = (gw >> 1) & 63;
    int n    = gw >> 7;
    int qr   = lane >> 2;
    int qc   = lane & 3;
    int ow_a = owh + qr;            // tile0 row a; row b = +8; tile1 = +16, +24

    const unsigned int* xl = g_xlo + (long)n * (H * W);
    const unsigned int* xh = g_xhi + (long)n * (H * W);

    int acc0[32], acc1[32];
#pragma unroll
    for (int i = 0; i < 32; i++) { acc0[i] = 0; acc1[i] = 0; }

    int sh0 = 4 * qc;
    int sh1 = 16 + 4 * qc;

#pragma unroll
    for (int kh = 0; kh < 3; kh++) {
        int ih = 2 * oh - 1 + kh;
        bool vr = (ih >= 0);                 // ih <= 127 always
        const unsigned int* rl = xl + ih * W;
        const unsigned int* rh = xh + ih * W;
#pragma unroll
        for (int kw = 0; kw < 3; kw++) {
            int tap = kh * 3 + kw;
            int iw0 = 2 * ow_a - 1 + kw;     // [-1, 79]; only owh==0,qr==0,kw==0 -> -1
            bool p0 = vr && (iw0 >= 0);

            // 4 M-rows: iw0, +16, +32, +48 (max 79+48 = 127, in range)
            unsigned int lo0 = p0 ? rl[iw0]      : 0u;
            unsigned int hi0 = p0 ? rh[iw0]      : 0u;
            unsigned int lo1 = vr ? rl[iw0 + 16] : 0u;
            unsigned int hi1 = vr ? rh[iw0 + 16] : 0u;
            unsigned int lo2 = vr ? rl[iw0 + 32] : 0u;
            unsigned int hi2 = vr ? rh[iw0 + 32] : 0u;
            unsigned int lo3 = vr ? rl[iw0 + 48] : 0u;
            unsigned int hi3 = vr ? rh[iw0 + 48] : 0u;

            // tile0 fragments (rows a=iw0, b=iw0+16)
            unsigned int t0a0 = p0 ? expand4((lo0 >> sh0) & 0xFu) : 0u;
            unsigned int t0a1 = vr ? expand4((lo1 >> sh0) & 0xFu) : 0u;
            unsigned int t0a2 = p0 ? expand4((lo0 >> sh1) & 0xFu) : 0u;
            unsigned int t0a3 = vr ? expand4((lo1 >> sh1) & 0xFu) : 0u;
            unsigned int t0a4 = p0 ? expand4((hi0 >> sh0) & 0xFu) : 0u;
            unsigned int t0a5 = vr ? expand4((hi1 >> sh0) & 0xFu) : 0u;
            unsigned int t0a6 = p0 ? expand4((hi0 >> sh1) & 0xFu) : 0u;
            unsigned int t0a7 = vr ? expand4((hi1 >> sh1) & 0xFu) : 0u;
            // tile1 fragments (rows a=iw0+32, b=iw0+48)
            unsigned int t1a0 = vr ? expand4((lo2 >> sh0) & 0xFu) : 0u;
            unsigned int t1a1 = vr ? expand4((lo3 >> sh0) & 0xFu) : 0u;
            unsigned int t1a2 = vr ? expand4((lo2 >> sh1) & 0xFu) : 0u;
            unsigned int t1a3 = vr ? expand4((lo3 >> sh1) & 0xFu) : 0u;
            unsigned int t1a4 = vr ? expand4((hi2 >> sh0) & 0xFu) : 0u;
            unsigned int t1a5 = vr ? expand4((hi3 >> sh0) & 0xFu) : 0u;
            unsigned int t1a6 = vr ? expand4((hi2 >> sh1) & 0xFu) : 0u;
            unsigned int t1a7 = vr ? expand4((hi3 >> sh1) & 0xFu) : 0u;

            const uint4* wf = g_wfrag + tap * 8 * 32 + lane;
#pragma unroll
            for (int j = 0; j < 8; j++) {
                uint4 b = wf[j * 32];
                mma_s8(acc0 + 4 * j, t0a0, t0a1, t0a2, t0a3, b.x, b.y);
                mma_s8(acc0 + 4 * j, t0a4, t0a5, t0a6, t0a7, b.z, b.w);
                mma_s8(acc1 + 4 * j, t1a0, t1a1, t1a2, t1a3, b.x, b.y);
                mma_s8(acc1 + 4 * j, t1a4, t1a5, t1a6, t1a7, b.z, b.w);
            }
        }
    }

    float* ob = out + ((long)(n * OC) * OH + oh) * OW;
#pragma unroll
    for (int j = 0; j < 8; j++) {
        int o0 = 8 * j + 2 * qc;
        float* p0 = ob + (long)o0 * (OH * OW);
        float* p1 = p0 + (OH * OW);
        p0[ow_a]      = (float)acc0[4 * j + 0];
        p1[ow_a]      = (float)acc0[4 * j + 1];
        p0[ow_a + 8]  = (float)acc0[4 * j + 2];
        p1[ow_a + 8]  = (float)acc0[4 * j + 3];
        p0[ow_a + 16] = (float)acc1[4 * j + 0];
        p1[ow_a + 16] = (float)acc1[4 * j + 1];
        p0[ow_a + 24] = (float)acc1[4 * j + 2];
        p1[ow_a + 24] = (float)acc1[4 * j + 3];
    }
}

// ---------------------------------------------------------------------------
extern "C" void kernel_launch(void* const* d_in, const int* in_sizes, int n_in,
                              void* d_out, int out_size) {
    const float* x = (const float*)d_in[0];
    const float* w = (const float*)d_in[1];
    float* out = (float*)d_out;

    pack_x_kernel<<<1024, 256>>>(x);
    pack_w_kernel<<<64, 64>>>(w);
    conv_mma_kernel<<<512, 256>>>(out);
}